// round 1
// baseline (speedup 1.0000x reference)
#include <cuda_runtime.h>
#include <math.h>

#define D_MODEL   1024
#define D_STATE   16
#define D_CONV    4
#define D_INNER   2048
#define DT_RANK   64
#define IN_SIZE   512
#define OUT_SIZE  512
#define BATCH     2048
#define XDB_COLS  96          // DT_RANK + 2*D_STATE
#define STATE_W   20          // D_CONV + D_STATE

// ---------------- scratch (static device globals; no allocation) ----------------
__device__ float g_h[BATCH * D_MODEL];         // 8 MB
__device__ float g_xz[BATCH * 2 * D_INNER];    // 32 MB
__device__ float g_xc[BATCH * D_INNER];        // 16 MB
__device__ float g_xdb[BATCH * XDB_COLS];      // 0.75 MB
__device__ float g_dt[BATCH * D_INNER];        // 16 MB
__device__ float g_y[BATCH * D_INNER];         // 16 MB
__device__ float g_core[BATCH * D_MODEL];      // 8 MB

// ---------------- helpers ----------------
__device__ __forceinline__ float softplusf(float x) {
    // numerically stable softplus
    return (x > 0.f) ? (x + log1pf(__expf(-x))) : log1pf(__expf(x));
}
__device__ __forceinline__ float siluf(float x) {
    return x / (1.f + __expf(-x));
}

// ---------------- generic tiled SGEMM ----------------
// C[M,N] = A[M,K] * op(B) (+bias) (+softplus)
// TB=false: B is K x N row-major (ldb = N).  TB=true: B is N x K row-major (ldb = K).
// gridDim.z > 1 => split-K, accumulate into C with atomicAdd (EPI must be 0; C pre-zeroed).
#define BM 128
#define BN 128
#define BK 16
#define TM 8
#define TN 8

template<bool TB, int EPI>
__global__ void __launch_bounds__(256)
sgemm_kernel(const float* __restrict__ A, const float* __restrict__ B,
             float* __restrict__ C, const float* __restrict__ bias,
             int M, int N, int K, int lda, int ldb, int ldc)
{
    __shared__ float As[BK][BM];
    __shared__ float Bs[BK][BN + 4];

    const int tid = threadIdx.x;
    const int m0 = blockIdx.y * BM;
    const int n0 = blockIdx.x * BN;
    const int Kc = K / gridDim.z;
    const int k0base = blockIdx.z * Kc;

    float acc[TM][TN];
#pragma unroll
    for (int i = 0; i < TM; i++)
#pragma unroll
        for (int j = 0; j < TN; j++) acc[i][j] = 0.f;

    const int arow = (tid * 4) / BK;   // 0..63
    const int acol = (tid * 4) % BK;

    for (int kt = 0; kt < Kc; kt += BK) {
        const int k0 = k0base + kt;
        // ---- load A tile (BM x BK), stored transposed As[k][m]
#pragma unroll
        for (int it = 0; it < 2; it++) {
            const int m = m0 + arow + it * 64;
            float4 v = *reinterpret_cast<const float4*>(&A[(size_t)m * lda + k0 + acol]);
            As[acol + 0][arow + it * 64] = v.x;
            As[acol + 1][arow + it * 64] = v.y;
            As[acol + 2][arow + it * 64] = v.z;
            As[acol + 3][arow + it * 64] = v.w;
        }
        // ---- load B tile (BK x BN) into Bs[k][n]
        if (!TB) {
            const int brow = (tid * 4) / BN;   // 0..7
            const int bcol = (tid * 4) % BN;
#pragma unroll
            for (int it = 0; it < 2; it++) {
                const int kk = brow + it * 8;
                const int n = n0 + bcol;
                float4 v = make_float4(0.f, 0.f, 0.f, 0.f);
                if (n < N) v = *reinterpret_cast<const float4*>(&B[(size_t)(k0 + kk) * ldb + n]);
                *reinterpret_cast<float4*>(&Bs[kk][bcol]) = v;
            }
        } else {
            const int bn = (tid * 4) / BK;     // 0..63
            const int bk = (tid * 4) % BK;
#pragma unroll
            for (int it = 0; it < 2; it++) {
                const int n = n0 + bn + it * 64;
                float4 v = make_float4(0.f, 0.f, 0.f, 0.f);
                if (n < N) v = *reinterpret_cast<const float4*>(&B[(size_t)n * ldb + k0 + bk]);
                Bs[bk + 0][bn + it * 64] = v.x;
                Bs[bk + 1][bn + it * 64] = v.y;
                Bs[bk + 2][bn + it * 64] = v.z;
                Bs[bk + 3][bn + it * 64] = v.w;
            }
        }
        __syncthreads();

        const int tr = tid / 16, tc = tid % 16;
#pragma unroll
        for (int k = 0; k < BK; k++) {
            float a[TM], bb[TN];
            float4 a0 = *reinterpret_cast<const float4*>(&As[k][tr * TM]);
            float4 a1 = *reinterpret_cast<const float4*>(&As[k][tr * TM + 4]);
            a[0] = a0.x; a[1] = a0.y; a[2] = a0.z; a[3] = a0.w;
            a[4] = a1.x; a[5] = a1.y; a[6] = a1.z; a[7] = a1.w;
            float4 b0 = *reinterpret_cast<const float4*>(&Bs[k][tc * TN]);
            float4 b1 = *reinterpret_cast<const float4*>(&Bs[k][tc * TN + 4]);
            bb[0] = b0.x; bb[1] = b0.y; bb[2] = b0.z; bb[3] = b0.w;
            bb[4] = b1.x; bb[5] = b1.y; bb[6] = b1.z; bb[7] = b1.w;
#pragma unroll
            for (int i = 0; i < TM; i++)
#pragma unroll
                for (int j = 0; j < TN; j++)
                    acc[i][j] += a[i] * bb[j];
        }
        __syncthreads();
    }

    // ---- epilogue
    const int tr = tid / 16, tc = tid % 16;
    const bool split = (gridDim.z > 1);
#pragma unroll
    for (int i = 0; i < TM; i++) {
        const int m = m0 + tr * TM + i;
#pragma unroll
        for (int j = 0; j < TN; j++) {
            const int n = n0 + tc * TN + j;
            if (m < M && n < N) {
                if (split) {
                    atomicAdd(&C[(size_t)m * ldc + n], acc[i][j]);
                } else {
                    float v = acc[i][j];
                    if (EPI >= 1) v += bias[n];
                    if (EPI == 2) v = softplusf(v);
                    C[(size_t)m * ldc + n] = v;
                }
            }
        }
    }
}

// ---------------- zero kernel (avoid memset node) ----------------
__global__ void zero_kernel(float* __restrict__ p, int n) {
    int i = blockIdx.x * blockDim.x + threadIdx.x;
    if (i < n) p[i] = 0.f;
}

// ---------------- conv-shift + silu ----------------
__global__ void __launch_bounds__(256)
conv_kernel(const float* __restrict__ rnn, const float* __restrict__ xz,
            const float* __restrict__ conv_w, const float* __restrict__ conv_b,
            float* __restrict__ out_states, float* __restrict__ xc)
{
    const size_t idx = (size_t)blockIdx.x * 256 + threadIdx.x;  // b*D_INNER + d
    const int b = (int)(idx / D_INNER);
    const int d = (int)(idx % D_INNER);
    const size_t srow = (size_t)b * (D_INNER * STATE_W) + (size_t)d * STATE_W;

    float4 cs = *reinterpret_cast<const float4*>(rnn + srow);        // old conv state
    float xi = xz[(size_t)b * (2 * D_INNER) + d];
    float4 w = *reinterpret_cast<const float4*>(conv_w + d * 4);

    float v = cs.y * w.x + cs.z * w.y + cs.w * w.z + xi * w.w + conv_b[d];
    xc[idx] = siluf(v);
    *reinterpret_cast<float4*>(out_states + srow) = make_float4(cs.y, cs.z, cs.w, xi);
}

// ---------------- SSM state update + gating ----------------
__global__ void __launch_bounds__(256)
ssm_kernel(const float* __restrict__ rnn, const float* __restrict__ xz,
           const float* __restrict__ xdb, const float* __restrict__ dt_,
           const float* __restrict__ xc_, const float* __restrict__ A_log,
           const float* __restrict__ Dp,
           float* __restrict__ out_states, float* __restrict__ y_)
{
    const int b = blockIdx.y;
    const int d = blockIdx.x * 256 + threadIdx.x;

    __shared__ float sBC[32];   // Bm[0..15], Cm[0..15]
    if (threadIdx.x < 32) sBC[threadIdx.x] = xdb[(size_t)b * XDB_COLS + DT_RANK + threadIdx.x];
    __syncthreads();

    const size_t bd = (size_t)b * D_INNER + d;
    const float dt = dt_[bd];
    const float xc = xc_[bd];
    const float z = xz[(size_t)b * (2 * D_INNER) + D_INNER + d];
    const float dtxc = dt * xc;

    const size_t srow = (size_t)b * (D_INNER * STATE_W) + (size_t)d * STATE_W;
    const float4* ss = reinterpret_cast<const float4*>(rnn + srow + D_CONV);
    float4* os = reinterpret_cast<float4*>(out_states + srow + D_CONV);
    const float4* Al = reinterpret_cast<const float4*>(A_log + d * D_STATE);

    float y = 0.f;
#pragma unroll
    for (int q = 0; q < 4; q++) {
        float4 s = ss[q];
        float4 a = Al[q];
        float sn[4] = {s.x, s.y, s.z, s.w};
        float an[4] = {a.x, a.y, a.z, a.w};
        float on[4];
#pragma unroll
        for (int i = 0; i < 4; i++) {
            const int n = q * 4 + i;
            const float dA = __expf(-dt * __expf(an[i]));
            const float sv = sn[i] * dA + dtxc * sBC[n];
            on[i] = sv;
            y += sv * sBC[16 + n];
        }
        os[q] = make_float4(on[0], on[1], on[2], on[3]);
    }
    y += Dp[d] * xc;
    y *= siluf(z);
    y_[bd] = y;
}

// ---------------- launch ----------------
extern "C" void kernel_launch(void* const* d_in, const int* in_sizes, int n_in,
                              void* d_out, int out_size)
{
    const float* x          = (const float*)d_in[0];
    const float* rnn        = (const float*)d_in[1];
    const float* w_inp      = (const float*)d_in[2];
    const float* b_inp      = (const float*)d_in[3];
    const float* w_outp     = (const float*)d_in[4];
    const float* b_outp     = (const float*)d_in[5];
    const float* in_proj_w  = (const float*)d_in[6];
    const float* conv_w     = (const float*)d_in[7];
    const float* conv_b     = (const float*)d_in[8];
    const float* x_proj_w   = (const float*)d_in[9];
    const float* dt_proj_w  = (const float*)d_in[10];
    const float* dt_proj_b  = (const float*)d_in[11];
    const float* A_log      = (const float*)d_in[12];
    const float* Dp         = (const float*)d_in[13];
    const float* out_proj_w = (const float*)d_in[14];

    float* out = (float*)d_out;                                 // (1, B, 512)
    float* out_states = out + (size_t)BATCH * OUT_SIZE;         // (B, 40960)

    float *p_h, *p_xz, *p_xc, *p_xdb, *p_dt, *p_y, *p_core;
    cudaGetSymbolAddress((void**)&p_h,    g_h);
    cudaGetSymbolAddress((void**)&p_xz,   g_xz);
    cudaGetSymbolAddress((void**)&p_xc,   g_xc);
    cudaGetSymbolAddress((void**)&p_xdb,  g_xdb);
    cudaGetSymbolAddress((void**)&p_dt,   g_dt);
    cudaGetSymbolAddress((void**)&p_y,    g_y);
    cudaGetSymbolAddress((void**)&p_core, g_core);

    dim3 blk(256);

    // 1) h = x @ w_inp + b_inp      (2048 x 512 -> 1024)
    sgemm_kernel<false, 1><<<dim3(D_MODEL / BN, BATCH / BM, 1), blk>>>(
        x, w_inp, p_h, b_inp, BATCH, D_MODEL, IN_SIZE, IN_SIZE, D_MODEL, D_MODEL);

    // 2) xz = h @ in_proj_w^T       (2048 x 1024 -> 4096)
    sgemm_kernel<true, 0><<<dim3(2 * D_INNER / BN, BATCH / BM, 1), blk>>>(
        p_h, in_proj_w, p_xz, nullptr, BATCH, 2 * D_INNER, D_MODEL, D_MODEL, D_MODEL, 2 * D_INNER);

    // 3) conv shift + silu -> xc ; write new conv_state
    conv_kernel<<<(BATCH * D_INNER) / 256, blk>>>(rnn, p_xz, conv_w, conv_b, out_states, p_xc);

    // 4) xdb = xc @ x_proj_w^T      (2048 x 2048 -> 96), split-K=8 with atomics
    zero_kernel<<<(BATCH * XDB_COLS + 255) / 256, blk>>>(p_xdb, BATCH * XDB_COLS);
    sgemm_kernel<true, 0><<<dim3(1, BATCH / BM, 8), blk>>>(
        p_xc, x_proj_w, p_xdb, nullptr, BATCH, XDB_COLS, D_INNER, D_INNER, D_INNER, XDB_COLS);

    // 5) dt = softplus(xdb[:, :64] @ dt_proj_w^T + dt_proj_b)   (2048 x 64 -> 2048)
    sgemm_kernel<true, 2><<<dim3(D_INNER / BN, BATCH / BM, 1), blk>>>(
        p_xdb, dt_proj_w, p_dt, dt_proj_b, BATCH, D_INNER, DT_RANK, XDB_COLS, DT_RANK, D_INNER);

    // 6) SSM update + y = (ssm . C + D*xc) * silu(z) ; write new ssm_state
    ssm_kernel<<<dim3(D_INNER / 256, BATCH), blk>>>(
        rnn, p_xz, p_xdb, p_dt, p_xc, A_log, Dp, out_states, p_y);

    // 7) core = y @ out_proj_w^T    (2048 x 2048 -> 1024)
    sgemm_kernel<true, 0><<<dim3(D_MODEL / BN, BATCH / BM, 1), blk>>>(
        p_y, out_proj_w, p_core, nullptr, BATCH, D_MODEL, D_INNER, D_INNER, D_INNER, D_MODEL);

    // 8) out = core @ w_outp + b_outp  (2048 x 1024 -> 512), writes d_out
    sgemm_kernel<false, 1><<<dim3(OUT_SIZE / BN, BATCH / BM, 1), blk>>>(
        p_core, w_outp, out, b_outp, BATCH, OUT_SIZE, D_MODEL, D_MODEL, OUT_SIZE, OUT_SIZE);
}

// round 2
// speedup vs baseline: 1.7626x; 1.7626x over previous
#include <cuda_runtime.h>
#include <math.h>
#include <stdint.h>

#define D_MODEL   1024
#define D_STATE   16
#define D_CONV    4
#define D_INNER   2048
#define DT_RANK   64
#define IN_SIZE   512
#define OUT_SIZE  512
#define BATCH     2048
#define XDB_COLS  96          // DT_RANK + 2*D_STATE
#define STATE_W   20          // D_CONV + D_STATE

// ---------------- scratch (static device globals; no allocation) ----------------
__device__ float g_h[BATCH * D_MODEL];
__device__ float g_xz[BATCH * 2 * D_INNER];
__device__ float g_xc[BATCH * D_INNER];
__device__ float g_xdb[BATCH * XDB_COLS];
__device__ float g_dt[BATCH * D_INNER];
__device__ float g_y[BATCH * D_INNER];
__device__ float g_core[BATCH * D_MODEL];

// ---------------- helpers ----------------
__device__ __forceinline__ float softplusf(float x) {
    return (x > 0.f) ? (x + log1pf(__expf(-x))) : log1pf(__expf(x));
}
__device__ __forceinline__ float siluf(float x) {
    return x / (1.f + __expf(-x));
}
__device__ __forceinline__ uint32_t f2tf(float x) {
    uint32_t r;
    asm("cvt.rna.tf32.f32 %0, %1;" : "=r"(r) : "f"(x));
    return r;
}
__device__ __forceinline__ void mma8(float* c, const uint32_t* a, const uint32_t* b) {
    asm volatile(
        "mma.sync.aligned.m16n8k8.row.col.f32.tf32.tf32.f32 "
        "{%0,%1,%2,%3}, {%4,%5,%6,%7}, {%8,%9}, {%0,%1,%2,%3};"
        : "+f"(c[0]), "+f"(c[1]), "+f"(c[2]), "+f"(c[3])
        : "r"(a[0]), "r"(a[1]), "r"(a[2]), "r"(a[3]), "r"(b[0]), "r"(b[1]));
}

// ======================================================================
// 3xTF32 tensor-core GEMM: C[M,N] = A[M,K] * op(B), fp32-equivalent accuracy.
// TB=false: B is KxN row-major. TB=true: B is NxK row-major.
// BM=BN=128, BK=32. 256 threads, warp grid 4(m) x 2(n), warp tile 32x64.
// EPI: 0=none, 1=+bias, 2=+bias,softplus
// Requires M%128==0, N%128==0, K%32==0.
// ======================================================================
#define TG_SMEM_BYTES 73728

template<bool TB, int EPI>
__global__ void __launch_bounds__(256)
tgemm_kernel(const float* __restrict__ A, const float* __restrict__ B,
             float* __restrict__ C, const float* __restrict__ bias,
             int M, int N, int K, int lda, int ldb, int ldc)
{
    extern __shared__ uint32_t sm[];
    const int ASZ = 128 * 36;
    const int BSZ = TB ? (128 * 36) : (32 * 132);
    const int BLD = TB ? 36 : 132;
    uint32_t* Ah  = sm;
    uint32_t* Alo = sm + ASZ;
    uint32_t* Bh  = sm + 2 * ASZ;
    uint32_t* Blo = sm + 2 * ASZ + BSZ;

    const int tid  = threadIdx.x;
    const int lane = tid & 31;
    const int warp = tid >> 5;
    const int wm   = warp & 3;          // 4 warps along M
    const int wn   = warp >> 2;         // 2 warps along N
    const int m0   = blockIdx.y * 128;
    const int n0   = blockIdx.x * 128;

    float acc[2][8][4];
#pragma unroll
    for (int i = 0; i < 2; i++)
#pragma unroll
        for (int j = 0; j < 8; j++)
#pragma unroll
            for (int q = 0; q < 4; q++) acc[i][j][q] = 0.f;

    const int ar = tid >> 3;            // 0..31
    const int ac = (tid & 7) * 4;       // 0..28
    const int br = TB ? (tid >> 3) : (tid >> 5);
    const int bc = TB ? ((tid & 7) * 4) : ((tid & 31) * 4);

    for (int kt = 0; kt < K; kt += 32) {
        // ---- load + split A tile (128 x 32)
#pragma unroll
        for (int it = 0; it < 4; it++) {
            const int row = ar + it * 32;
            float4 v = *reinterpret_cast<const float4*>(&A[(size_t)(m0 + row) * lda + kt + ac]);
            uint4 hi, lo;
            hi.x = f2tf(v.x); lo.x = f2tf(v.x - __uint_as_float(hi.x));
            hi.y = f2tf(v.y); lo.y = f2tf(v.y - __uint_as_float(hi.y));
            hi.z = f2tf(v.z); lo.z = f2tf(v.z - __uint_as_float(hi.z));
            hi.w = f2tf(v.w); lo.w = f2tf(v.w - __uint_as_float(hi.w));
            *reinterpret_cast<uint4*>(&Ah[row * 36 + ac])  = hi;
            *reinterpret_cast<uint4*>(&Alo[row * 36 + ac]) = lo;
        }
        // ---- load + split B tile
        if (TB) {   // B: N x K, tile 128(n) x 32(k), smem [n][k]
#pragma unroll
            for (int it = 0; it < 4; it++) {
                const int row = br + it * 32;   // n
                float4 v = *reinterpret_cast<const float4*>(&B[(size_t)(n0 + row) * ldb + kt + bc]);
                uint4 hi, lo;
                hi.x = f2tf(v.x); lo.x = f2tf(v.x - __uint_as_float(hi.x));
                hi.y = f2tf(v.y); lo.y = f2tf(v.y - __uint_as_float(hi.y));
                hi.z = f2tf(v.z); lo.z = f2tf(v.z - __uint_as_float(hi.z));
                hi.w = f2tf(v.w); lo.w = f2tf(v.w - __uint_as_float(hi.w));
                *reinterpret_cast<uint4*>(&Bh[row * 36 + bc])  = hi;
                *reinterpret_cast<uint4*>(&Blo[row * 36 + bc]) = lo;
            }
        } else {    // B: K x N, tile 32(k) x 128(n), smem [k][n]
#pragma unroll
            for (int it = 0; it < 4; it++) {
                const int row = br + it * 8;    // k
                float4 v = *reinterpret_cast<const float4*>(&B[(size_t)(kt + row) * ldb + n0 + bc]);
                uint4 hi, lo;
                hi.x = f2tf(v.x); lo.x = f2tf(v.x - __uint_as_float(hi.x));
                hi.y = f2tf(v.y); lo.y = f2tf(v.y - __uint_as_float(hi.y));
                hi.z = f2tf(v.z); lo.z = f2tf(v.z - __uint_as_float(hi.z));
                hi.w = f2tf(v.w); lo.w = f2tf(v.w - __uint_as_float(hi.w));
                *reinterpret_cast<uint4*>(&Bh[row * 132 + bc])  = hi;
                *reinterpret_cast<uint4*>(&Blo[row * 132 + bc]) = lo;
            }
        }
        __syncthreads();

#pragma unroll
        for (int ks = 0; ks < 32; ks += 8) {
            uint32_t ah[2][4], al[2][4];
#pragma unroll
            for (int mt = 0; mt < 2; mt++) {
                const int mr = wm * 32 + mt * 16 + (lane >> 2);
                const int kc = ks + (lane & 3);
                ah[mt][0] = Ah[mr * 36 + kc];
                ah[mt][1] = Ah[(mr + 8) * 36 + kc];
                ah[mt][2] = Ah[mr * 36 + kc + 4];
                ah[mt][3] = Ah[(mr + 8) * 36 + kc + 4];
                al[mt][0] = Alo[mr * 36 + kc];
                al[mt][1] = Alo[(mr + 8) * 36 + kc];
                al[mt][2] = Alo[mr * 36 + kc + 4];
                al[mt][3] = Alo[(mr + 8) * 36 + kc + 4];
            }
            uint32_t bh[8][2], bl[8][2];
#pragma unroll
            for (int nt = 0; nt < 8; nt++) {
                const int nc = wn * 64 + nt * 8 + (lane >> 2);
                const int kc = ks + (lane & 3);
                if (TB) {
                    bh[nt][0] = Bh[nc * BLD + kc];
                    bh[nt][1] = Bh[nc * BLD + kc + 4];
                    bl[nt][0] = Blo[nc * BLD + kc];
                    bl[nt][1] = Blo[nc * BLD + kc + 4];
                } else {
                    bh[nt][0] = Bh[kc * BLD + nc];
                    bh[nt][1] = Bh[(kc + 4) * BLD + nc];
                    bl[nt][0] = Blo[kc * BLD + nc];
                    bl[nt][1] = Blo[(kc + 4) * BLD + nc];
                }
            }
#pragma unroll
            for (int mt = 0; mt < 2; mt++)
#pragma unroll
                for (int nt = 0; nt < 8; nt++) {
                    mma8(acc[mt][nt], al[mt], bh[nt]);   // a_lo * b_hi
                    mma8(acc[mt][nt], ah[mt], bl[nt]);   // a_hi * b_lo
                    mma8(acc[mt][nt], ah[mt], bh[nt]);   // a_hi * b_hi
                }
        }
        __syncthreads();
    }

    // ---- epilogue (dims are exact multiples; no guards needed)
#pragma unroll
    for (int mt = 0; mt < 2; mt++) {
        const int mr = m0 + wm * 32 + mt * 16 + (lane >> 2);
#pragma unroll
        for (int nt = 0; nt < 8; nt++) {
            const int nc = n0 + wn * 64 + nt * 8 + (lane & 3) * 2;
            float v0 = acc[mt][nt][0], v1 = acc[mt][nt][1];
            float v2 = acc[mt][nt][2], v3 = acc[mt][nt][3];
            if (EPI >= 1) {
                const float b0 = bias[nc], b1 = bias[nc + 1];
                v0 += b0; v1 += b1; v2 += b0; v3 += b1;
            }
            if (EPI == 2) {
                v0 = softplusf(v0); v1 = softplusf(v1);
                v2 = softplusf(v2); v3 = softplusf(v3);
            }
            *reinterpret_cast<float2*>(&C[(size_t)mr * ldc + nc])       = make_float2(v0, v1);
            *reinterpret_cast<float2*>(&C[(size_t)(mr + 8) * ldc + nc]) = make_float2(v2, v3);
        }
    }
}

// ======================================================================
// fp32 SIMT GEMM (kept only for the skinny N=96 x_proj GEMM, split-K)
// ======================================================================
#define BM 128
#define BN 128
#define BK 16
#define TM 8
#define TN 8

__global__ void __launch_bounds__(256)
sgemm_tb_splitk(const float* __restrict__ A, const float* __restrict__ B,
                float* __restrict__ C,
                int M, int N, int K, int lda, int ldb, int ldc)
{
    __shared__ float As[BK][BM];
    __shared__ float Bs[BK][BN + 4];

    const int tid = threadIdx.x;
    const int m0 = blockIdx.y * BM;
    const int n0 = blockIdx.x * BN;
    const int Kc = K / gridDim.z;
    const int k0base = blockIdx.z * Kc;

    float acc[TM][TN];
#pragma unroll
    for (int i = 0; i < TM; i++)
#pragma unroll
        for (int j = 0; j < TN; j++) acc[i][j] = 0.f;

    const int arow = (tid * 4) / BK;
    const int acol = (tid * 4) % BK;

    for (int kt = 0; kt < Kc; kt += BK) {
        const int k0 = k0base + kt;
#pragma unroll
        for (int it = 0; it < 2; it++) {
            const int m = m0 + arow + it * 64;
            float4 v = *reinterpret_cast<const float4*>(&A[(size_t)m * lda + k0 + acol]);
            As[acol + 0][arow + it * 64] = v.x;
            As[acol + 1][arow + it * 64] = v.y;
            As[acol + 2][arow + it * 64] = v.z;
            As[acol + 3][arow + it * 64] = v.w;
        }
        {
            const int bn = (tid * 4) / BK;
            const int bk = (tid * 4) % BK;
#pragma unroll
            for (int it = 0; it < 2; it++) {
                const int n = n0 + bn + it * 64;
                float4 v = make_float4(0.f, 0.f, 0.f, 0.f);
                if (n < N) v = *reinterpret_cast<const float4*>(&B[(size_t)n * ldb + k0 + bk]);
                Bs[bk + 0][bn + it * 64] = v.x;
                Bs[bk + 1][bn + it * 64] = v.y;
                Bs[bk + 2][bn + it * 64] = v.z;
                Bs[bk + 3][bn + it * 64] = v.w;
            }
        }
        __syncthreads();

        const int tr = tid / 16, tc = tid % 16;
#pragma unroll
        for (int k = 0; k < BK; k++) {
            float a[TM], bb[TN];
            float4 a0 = *reinterpret_cast<const float4*>(&As[k][tr * TM]);
            float4 a1 = *reinterpret_cast<const float4*>(&As[k][tr * TM + 4]);
            a[0] = a0.x; a[1] = a0.y; a[2] = a0.z; a[3] = a0.w;
            a[4] = a1.x; a[5] = a1.y; a[6] = a1.z; a[7] = a1.w;
            float4 b0 = *reinterpret_cast<const float4*>(&Bs[k][tc * TN]);
            float4 b1 = *reinterpret_cast<const float4*>(&Bs[k][tc * TN + 4]);
            bb[0] = b0.x; bb[1] = b0.y; bb[2] = b0.z; bb[3] = b0.w;
            bb[4] = b1.x; bb[5] = b1.y; bb[6] = b1.z; bb[7] = b1.w;
#pragma unroll
            for (int i = 0; i < TM; i++)
#pragma unroll
                for (int j = 0; j < TN; j++)
                    acc[i][j] += a[i] * bb[j];
        }
        __syncthreads();
    }

    const int tr = tid / 16, tc = tid % 16;
#pragma unroll
    for (int i = 0; i < TM; i++) {
        const int m = m0 + tr * TM + i;
#pragma unroll
        for (int j = 0; j < TN; j++) {
            const int n = n0 + tc * TN + j;
            if (m < M && n < N)
                atomicAdd(&C[(size_t)m * ldc + n], acc[i][j]);
        }
    }
}

__global__ void zero_kernel(float* __restrict__ p, int n) {
    int i = blockIdx.x * blockDim.x + threadIdx.x;
    if (i < n) p[i] = 0.f;
}

// ---------------- conv-shift + silu ----------------
__global__ void __launch_bounds__(256)
conv_kernel(const float* __restrict__ rnn, const float* __restrict__ xz,
            const float* __restrict__ conv_w, const float* __restrict__ conv_b,
            float* __restrict__ out_states, float* __restrict__ xc)
{
    const size_t idx = (size_t)blockIdx.x * 256 + threadIdx.x;
    const int b = (int)(idx / D_INNER);
    const int d = (int)(idx % D_INNER);
    const size_t srow = (size_t)b * (D_INNER * STATE_W) + (size_t)d * STATE_W;

    float4 cs = *reinterpret_cast<const float4*>(rnn + srow);
    float xi = xz[(size_t)b * (2 * D_INNER) + d];
    float4 w = *reinterpret_cast<const float4*>(conv_w + d * 4);

    float v = cs.y * w.x + cs.z * w.y + cs.w * w.z + xi * w.w + conv_b[d];
    xc[idx] = siluf(v);
    *reinterpret_cast<float4*>(out_states + srow) = make_float4(cs.y, cs.z, cs.w, xi);
}

// ---------------- SSM state update + gating ----------------
__global__ void __launch_bounds__(256)
ssm_kernel(const float* __restrict__ rnn, const float* __restrict__ xz,
           const float* __restrict__ xdb, const float* __restrict__ dt_,
           const float* __restrict__ xc_, const float* __restrict__ A_log,
           const float* __restrict__ Dp,
           float* __restrict__ out_states, float* __restrict__ y_)
{
    const int b = blockIdx.y;
    const int d = blockIdx.x * 256 + threadIdx.x;

    __shared__ float sBC[32];
    if (threadIdx.x < 32) sBC[threadIdx.x] = xdb[(size_t)b * XDB_COLS + DT_RANK + threadIdx.x];
    __syncthreads();

    const size_t bd = (size_t)b * D_INNER + d;
    const float dt = dt_[bd];
    const float xc = xc_[bd];
    const float z = xz[(size_t)b * (2 * D_INNER) + D_INNER + d];
    const float dtxc = dt * xc;

    const size_t srow = (size_t)b * (D_INNER * STATE_W) + (size_t)d * STATE_W;
    const float4* ss = reinterpret_cast<const float4*>(rnn + srow + D_CONV);
    float4* os = reinterpret_cast<float4*>(out_states + srow + D_CONV);
    const float4* Al = reinterpret_cast<const float4*>(A_log + d * D_STATE);

    float y = 0.f;
#pragma unroll
    for (int q = 0; q < 4; q++) {
        float4 s = ss[q];
        float4 a = Al[q];
        float sn[4] = {s.x, s.y, s.z, s.w};
        float an[4] = {a.x, a.y, a.z, a.w};
        float on[4];
#pragma unroll
        for (int i = 0; i < 4; i++) {
            const int n = q * 4 + i;
            const float dA = __expf(-dt * __expf(an[i]));
            const float sv = sn[i] * dA + dtxc * sBC[n];
            on[i] = sv;
            y += sv * sBC[16 + n];
        }
        os[q] = make_float4(on[0], on[1], on[2], on[3]);
    }
    y += Dp[d] * xc;
    y *= siluf(z);
    y_[bd] = y;
}

// ---------------- launch ----------------
extern "C" void kernel_launch(void* const* d_in, const int* in_sizes, int n_in,
                              void* d_out, int out_size)
{
    const float* x          = (const float*)d_in[0];
    const float* rnn        = (const float*)d_in[1];
    const float* w_inp      = (const float*)d_in[2];
    const float* b_inp      = (const float*)d_in[3];
    const float* w_outp     = (const float*)d_in[4];
    const float* b_outp     = (const float*)d_in[5];
    const float* in_proj_w  = (const float*)d_in[6];
    const float* conv_w     = (const float*)d_in[7];
    const float* conv_b     = (const float*)d_in[8];
    const float* x_proj_w   = (const float*)d_in[9];
    const float* dt_proj_w  = (const float*)d_in[10];
    const float* dt_proj_b  = (const float*)d_in[11];
    const float* A_log      = (const float*)d_in[12];
    const float* Dp         = (const float*)d_in[13];
    const float* out_proj_w = (const float*)d_in[14];

    float* out = (float*)d_out;
    float* out_states = out + (size_t)BATCH * OUT_SIZE;

    float *p_h, *p_xz, *p_xc, *p_xdb, *p_dt, *p_y, *p_core;
    cudaGetSymbolAddress((void**)&p_h,    g_h);
    cudaGetSymbolAddress((void**)&p_xz,   g_xz);
    cudaGetSymbolAddress((void**)&p_xc,   g_xc);
    cudaGetSymbolAddress((void**)&p_xdb,  g_xdb);
    cudaGetSymbolAddress((void**)&p_dt,   g_dt);
    cudaGetSymbolAddress((void**)&p_y,    g_y);
    cudaGetSymbolAddress((void**)&p_core, g_core);

    cudaFuncSetAttribute(tgemm_kernel<false, 1>, cudaFuncAttributeMaxDynamicSharedMemorySize, TG_SMEM_BYTES);
    cudaFuncSetAttribute(tgemm_kernel<true,  0>, cudaFuncAttributeMaxDynamicSharedMemorySize, TG_SMEM_BYTES);
    cudaFuncSetAttribute(tgemm_kernel<true,  2>, cudaFuncAttributeMaxDynamicSharedMemorySize, TG_SMEM_BYTES);

    dim3 blk(256);

    // 1) h = x @ w_inp + b_inp      (2048 x 512 -> 1024)
    tgemm_kernel<false, 1><<<dim3(D_MODEL / 128, BATCH / 128), blk, TG_SMEM_BYTES>>>(
        x, w_inp, p_h, b_inp, BATCH, D_MODEL, IN_SIZE, IN_SIZE, D_MODEL, D_MODEL);

    // 2) xz = h @ in_proj_w^T       (2048 x 1024 -> 4096)
    tgemm_kernel<true, 0><<<dim3(2 * D_INNER / 128, BATCH / 128), blk, TG_SMEM_BYTES>>>(
        p_h, in_proj_w, p_xz, nullptr, BATCH, 2 * D_INNER, D_MODEL, D_MODEL, D_MODEL, 2 * D_INNER);

    // 3) conv shift + silu -> xc ; write new conv_state
    conv_kernel<<<(BATCH * D_INNER) / 256, blk>>>(rnn, p_xz, conv_w, conv_b, out_states, p_xc);

    // 4) xdb = xc @ x_proj_w^T      (2048 x 2048 -> 96), split-K=8 fp32
    zero_kernel<<<(BATCH * XDB_COLS + 255) / 256, blk>>>(p_xdb, BATCH * XDB_COLS);
    sgemm_tb_splitk<<<dim3(1, BATCH / BM, 8), blk>>>(
        p_xc, x_proj_w, p_xdb, BATCH, XDB_COLS, D_INNER, D_INNER, D_INNER, XDB_COLS);

    // 5) dt = softplus(xdb[:, :64] @ dt_proj_w^T + dt_proj_b)   (2048 x 64 -> 2048)
    tgemm_kernel<true, 2><<<dim3(D_INNER / 128, BATCH / 128), blk, TG_SMEM_BYTES>>>(
        p_xdb, dt_proj_w, p_dt, dt_proj_b, BATCH, D_INNER, DT_RANK, XDB_COLS, DT_RANK, D_INNER);

    // 6) SSM update + y
    ssm_kernel<<<dim3(D_INNER / 256, BATCH), blk>>>(
        rnn, p_xz, p_xdb, p_dt, p_xc, A_log, Dp, out_states, p_y);

    // 7) core = y @ out_proj_w^T    (2048 x 2048 -> 1024)
    tgemm_kernel<true, 0><<<dim3(D_MODEL / 128, BATCH / 128), blk, TG_SMEM_BYTES>>>(
        p_y, out_proj_w, p_core, nullptr, BATCH, D_MODEL, D_INNER, D_INNER, D_INNER, D_MODEL);

    // 8) out = core @ w_outp + b_outp  (2048 x 1024 -> 512)
    tgemm_kernel<false, 1><<<dim3(OUT_SIZE / 128, BATCH / 128), blk, TG_SMEM_BYTES>>>(
        p_core, w_outp, out, b_outp, BATCH, OUT_SIZE, D_MODEL, D_MODEL, OUT_SIZE, OUT_SIZE);
}